// round 16
// baseline (speedup 1.0000x reference)
#include <cuda_runtime.h>
#include <cuda_fp16.h>
#include <cstdint>
#include <math.h>

#define NN    8192
#define CCH   256
#define CD    32
#define BQ    128
#define BK    64
#define NITER 128
#define NSTAGE 5

// attn smem layout (bytes) — 5-stage
#define QROW  80
#define KROW  80
#define VROW  144
#define SM_Q  0
#define KSTG  (BK * KROW)                  // 5120
#define SM_K  10240
#define VSTG  (CCH * VROW)                 // 36864
#define SM_V  (SM_K + NSTAGE * KSTG)       // 35840
#define SM_TOTAL (SM_V + NSTAGE * VSTG)    // 220160

#define LOG2E 1.4426950408889634f

// proj smem layout
#define PA_STG 6144
#define PB_OFF 12288
#define PSTAGE_OFF 24576
#define PROJ_SMEM (24576 + 34816)   // 59392

// ---------------- scratch (f16 operands) ----------------
__device__ __half g_QA[NN * CD];
__device__ __half g_KA[NN * CD];
__device__ __half g_QB[NN * CD];
__device__ __half g_KB[NN * CD];
__device__ __half g_VAb[CCH * NN];
__device__ __half g_VBb[CCH * NN];

// ---------------- PTX helpers ----------------
__device__ __forceinline__ uint32_t smem_u32(const void* p) {
    uint32_t a;
    asm("{ .reg .u64 t; cvta.to.shared.u64 t, %1; cvt.u32.u64 %0, t; }" : "=r"(a) : "l"(p));
    return a;
}
__device__ __forceinline__ void cp16(uint32_t dst, const void* src) {
    asm volatile("cp.async.cg.shared.global [%0], [%1], 16;" :: "r"(dst), "l"(src));
}
__device__ __forceinline__ void cp_commit() { asm volatile("cp.async.commit_group;" ::: "memory"); }
__device__ __forceinline__ void cp_wait3()  { asm volatile("cp.async.wait_group 3;"  ::: "memory"); }

__device__ __forceinline__ void ldmx4(uint32_t& r0, uint32_t& r1, uint32_t& r2, uint32_t& r3,
                                      uint32_t a) {
    asm volatile("ldmatrix.sync.aligned.m8n8.x4.shared.b16 {%0,%1,%2,%3}, [%4];"
        : "=r"(r0), "=r"(r1), "=r"(r2), "=r"(r3) : "r"(a));
}
__device__ __forceinline__ void mma16816h(float* c, const uint32_t* a, uint32_t b0, uint32_t b1) {
    asm volatile("mma.sync.aligned.m16n8k16.row.col.f32.f16.f16.f32 "
        "{%0,%1,%2,%3}, {%4,%5,%6,%7}, {%8,%9}, {%0,%1,%2,%3};"
        : "+f"(c[0]), "+f"(c[1]), "+f"(c[2]), "+f"(c[3])
        : "r"(a[0]), "r"(a[1]), "r"(a[2]), "r"(a[3]), "r"(b0), "r"(b1));
}
__device__ __forceinline__ uint32_t pkh2(float lo, float hi) {
    uint32_t d;
    asm("cvt.rn.f16x2.f32 %0, %1, %2;" : "=r"(d) : "f"(hi), "f"(lo));
    return d;
}
__device__ __forceinline__ uint32_t ex2h2(uint32_t a) {
    uint32_t d;
    asm("ex2.approx.f16x2 %0, %1;" : "=r"(d) : "r"(a));
    return d;
}
__device__ __forceinline__ void sts32(uint32_t a, uint32_t v) {
    asm volatile("st.shared.b32 [%0], %1;" :: "r"(a), "r"(v) : "memory");
}
__device__ __forceinline__ void sts16(uint32_t a, unsigned short v) {
    asm volatile("st.shared.b16 [%0], %1;" :: "r"(a), "h"(v) : "memory");
}
__device__ __forceinline__ uint4 lds128(uint32_t a) {
    uint4 v;
    asm volatile("ld.shared.v4.u32 {%0,%1,%2,%3}, [%4];"
        : "=r"(v.x), "=r"(v.y), "=r"(v.z), "=r"(v.w) : "r"(a));
    return v;
}

// ---------------- tensor-core projections (R7, unchanged) ----------------
__global__ void __launch_bounds__(256, 2)
proj_mma_kernel(const float* __restrict__ x,
                const float* __restrict__ WqA, const float* __restrict__ bqA,
                const float* __restrict__ WkA, const float* __restrict__ bkA,
                const float* __restrict__ WvA, const float* __restrict__ bvA,
                const float* __restrict__ WqB, const float* __restrict__ bqB,
                const float* __restrict__ WkB, const float* __restrict__ bkB,
                const float* __restrict__ WvB, const float* __restrict__ bvB)
{
    extern __shared__ __align__(128) char psm[];
    const uint32_t smb = smem_u32(psm);
    const int tid  = threadIdx.x;
    const int lane = tid & 31;
    const int wid  = tid >> 5;
    const int mg   = wid & 3;
    const int nh   = wid >> 2;
    const int by   = blockIdx.y;
    const int n0   = blockIdx.x * 128;

    const int rA  = tid >> 3;
    const int j2  = tid & 7;
    const int ct2 = tid >> 7;
    const int xn  = n0 + (tid & 127);
    const float* aptr[4];
    int rowbase = 0;
    const float* bv = 0;
    if (by == 0) {
        aptr[0] = WqA + rA * CCH; aptr[1] = WkA + rA * CCH;
        aptr[2] = WqB + rA * CCH; aptr[3] = WkB + rA * CCH;
    } else {
        const float* Wv = (by <= 2) ? WvA : WvB;
        bv = (by <= 2) ? bvA : bvB;
        rowbase = ((by - 1) & 1) * 128;
#pragma unroll
        for (int i = 0; i < 4; i++) aptr[i] = Wv + (rowbase + rA + i * 32) * CCH;
    }

    float oacc[64];
#pragma unroll
    for (int i = 0; i < 64; i++) oacc[i] = 0.f;

    {
#pragma unroll
        for (int i = 0; i < 4; i++) {
            float2 w2 = *(const float2*)(aptr[i] + 2 * j2);
            sts32(smb + (rA + i * 32) * 48 + j2 * 4, pkh2(w2.x, w2.y));
        }
#pragma unroll
        for (int i = 0; i < 4; i++) {
            int cp = i * 4 + ct2 * 2;
            float v0 = x[(size_t)cp * NN + xn];
            float v1 = x[(size_t)(cp + 1) * NN + xn];
            sts32(smb + PB_OFF + (tid & 127) * 48 + cp * 2, pkh2(v0, v1));
        }
    }
    __syncthreads();

#pragma unroll 1
    for (int kc = 0; kc < 16; kc++) {
        float2 wA[4]; float xb0[4], xb1[4];
        if (kc < 15) {
            int k1 = (kc + 1) * 16;
#pragma unroll
            for (int i = 0; i < 4; i++) wA[i] = *(const float2*)(aptr[i] + k1 + 2 * j2);
#pragma unroll
            for (int i = 0; i < 4; i++) {
                int cp = i * 4 + ct2 * 2;
                xb0[i] = x[(size_t)(k1 + cp) * NN + xn];
                xb1[i] = x[(size_t)(k1 + cp + 1) * NN + xn];
            }
        }
        const uint32_t Ab = smb + (kc & 1) * PA_STG;
        const uint32_t Bb = smb + PB_OFF + (kc & 1) * PA_STG;

        uint32_t a0[4], a1[4];
        uint32_t aa = Ab + (mg * 32 + (lane & 15)) * 48 + (lane >> 4) * 16;
        ldmx4(a0[0], a0[1], a0[2], a0[3], aa);
        ldmx4(a1[0], a1[1], a1[2], a1[3], aa + 16 * 48);
#pragma unroll
        for (int ng = 0; ng < 4; ng++) {
            uint32_t b0, b1, b2, b3;
            uint32_t ba = Bb + (nh * 64 + ng * 16 + (lane & 7) + ((lane >> 4) & 1) * 8) * 48
                        + ((lane >> 3) & 1) * 16;
            ldmx4(b0, b1, b2, b3, ba);
            mma16816h(&oacc[(ng * 2 + 0) * 4],      a0, b0, b1);
            mma16816h(&oacc[(ng * 2 + 1) * 4],      a0, b2, b3);
            mma16816h(&oacc[(8 + ng * 2 + 0) * 4],  a1, b0, b1);
            mma16816h(&oacc[(8 + ng * 2 + 1) * 4],  a1, b2, b3);
        }

        if (kc < 15) {
            const uint32_t Aw = smb + ((kc + 1) & 1) * PA_STG;
            const uint32_t Bw = smb + PB_OFF + ((kc + 1) & 1) * PA_STG;
#pragma unroll
            for (int i = 0; i < 4; i++)
                sts32(Aw + (rA + i * 32) * 48 + j2 * 4, pkh2(wA[i].x, wA[i].y));
#pragma unroll
            for (int i = 0; i < 4; i++) {
                int cp = i * 4 + ct2 * 2;
                sts32(Bw + (tid & 127) * 48 + cp * 2, pkh2(xb0[i], xb1[i]));
            }
        }
        __syncthreads();
    }

    if (by == 0) {
        const float* bArr[4] = {bqA, bkA, bqB, bkB};
        const float sc = (mg == 0 || mg == 2) ? LOG2E : 1.f;
        const uint32_t stg = smb + PSTAGE_OFF;
#pragma unroll
        for (int m2 = 0; m2 < 2; m2++) {
#pragma unroll
            for (int s8 = 0; s8 < 2; s8++) {
                int cl = m2 * 16 + (lane >> 2) + s8 * 8;
                int c  = mg * 32 + cl;
                float bb = bArr[mg][cl];
#pragma unroll
                for (int nt = 0; nt < 8; nt++) {
                    const float* o = &oacc[(m2 * 8 + nt) * 4];
                    int n = nh * 64 + nt * 8 + 2 * (lane & 3);
                    float v0 = (o[s8 * 2]     + bb) * sc;
                    float v1 = (o[s8 * 2 + 1] + bb) * sc;
                    sts16(stg + n * 272 + c * 2,       __half_as_ushort(__float2half_rn(v0)));
                    sts16(stg + (n + 1) * 272 + c * 2, __half_as_ushort(__float2half_rn(v1)));
                }
            }
        }
        __syncthreads();
        __half* gq[4] = {g_QA, g_KA, g_QB, g_KB};
#pragma unroll
        for (int i = 0; i < 8; i++) {
            int id = i * 256 + tid;
            int n = id >> 4, c16 = id & 15;
            uint4 v = lds128(stg + n * 272 + c16 * 16);
            int c = c16 * 8;
            __half* gp = gq[c >> 5] + (size_t)(n0 + n) * CD + (c & 31);
            *(uint4*)gp = v;
        }
    } else {
        __half* gV = (by <= 2) ? g_VAb : g_VBb;
#pragma unroll
        for (int m2 = 0; m2 < 2; m2++) {
#pragma unroll
            for (int s8 = 0; s8 < 2; s8++) {
                int c = mg * 32 + m2 * 16 + (lane >> 2) + s8 * 8;
                float bb = bv[rowbase + c];
#pragma unroll
                for (int nt = 0; nt < 8; nt++) {
                    const float* o = &oacc[(m2 * 8 + nt) * 4];
                    int n = nh * 64 + nt * 8 + 2 * (lane & 3);
                    __half2 hv = __floats2half2_rn(o[s8 * 2] + bb, o[s8 * 2 + 1] + bb);
                    *(__half2*)(gV + (size_t)(rowbase + c) * NN + n0 + n) = hv;
                }
            }
        }
    }
}

// ---------------- K/V tile loader (512 threads, 5-stage) ----------------
__device__ __forceinline__ void load_kv(uint32_t smb, int st, int t,
                                        const __half* __restrict__ Kg,
                                        const __half* __restrict__ Vg,
                                        int tid)
{
    const int m0 = t * BK;
    if (tid < 256) {
        int r = tid >> 2, j = tid & 3;
        cp16(smb + SM_K + st * KSTG + r * KROW + j * 16,
             Kg + (size_t)(m0 + r) * CD + j * 8);
    }
#pragma unroll
    for (int i = 0; i < 4; i++) {
        int idx = tid + i * 512;
        int r = idx >> 3, j = idx & 7;
        cp16(smb + SM_V + st * VSTG + r * VROW + j * 16,
             Vg + (size_t)r * NN + m0 + j * 8);
    }
}

// ---------------- fused mma.sync flash attention (R8 + hoisted qa + 5-stage) ----------------
extern "C" __global__ void __launch_bounds__(512, 1)
attn_mma_kernel(const float* __restrict__ x,
                const float* __restrict__ gA, const float* __restrict__ gB,
                float* __restrict__ out)
{
    extern __shared__ __align__(128) char smem[];
    const uint32_t smb = smem_u32(smem);
    const int tid  = threadIdx.x;
    const int wid  = tid >> 5;
    const int lane = tid & 31;
    const int h    = wid >> 3;
    const int w8   = wid & 7;
    const int n0   = blockIdx.x * BQ;

    const __half *Qg, *Kg, *Vg; float gamma; float* outp;
    if (blockIdx.y == 0) { Qg = g_QA; Kg = g_KB; Vg = g_VBb; gamma = gA[0]; outp = out; }
    else                 { Qg = g_QB; Kg = g_KA; Vg = g_VAb; gamma = gB[0]; outp = out + (size_t)CCH * NN; }

    // prologue: group0 = Q + tile0; groups 1..3 = tiles 1..3
    {
        int r = tid >> 2, j = tid & 3;
        cp16(smb + SM_Q + r * QROW + j * 16, Qg + (size_t)(n0 + r) * CD + j * 8);
    }
    load_kv(smb, 0, 0, Kg, Vg, tid); cp_commit();
    load_kv(smb, 1, 1, Kg, Vg, tid); cp_commit();
    load_kv(smb, 2, 2, Kg, Vg, tid); cp_commit();
    load_kv(smb, 3, 3, Kg, Vg, tid); cp_commit();

    // wait group0 (Q + tile0) and hoist Q A-frags
    cp_wait3();
    __syncthreads();
    uint32_t qa[8];
    {
        uint32_t a0 = smb + SM_Q + (w8 * 16 + (lane & 15)) * QROW + (lane >> 4) * 16;
        ldmx4(qa[0], qa[1], qa[2], qa[3], a0);
        ldmx4(qa[4], qa[5], qa[6], qa[7], a0 + 32);
    }

    float oacc[64];
#pragma unroll
    for (int i = 0; i < 64; i++) oacc[i] = 0.f;
    float lsum0 = 0.f, lsum1 = 0.f;

#pragma unroll 1
    for (int t = 0; t < NITER; t++) {
        cp_wait3();          // group t done (pending <= t+1..t+3)
        __syncthreads();     // all warps finished stage (t-1)%5; tile t visible to all

        if (t + 4 < NITER) load_kv(smb, (t + 4) % NSTAGE, t + 4, Kg, Vg, tid);
        cp_commit();

        const int st = t % NSTAGE;
        const uint32_t kb = smb + SM_K + st * KSTG;
        const uint32_t vb = smb + SM_V + st * VSTG + h * 128 * VROW;

        // ---- S phase: K frags double-buffered, converted to pf per-nt ----
        uint32_t pf[16];
        {
            const uint32_t ka = kb + (lane & 7) * KROW + (lane >> 3) * 16;
            uint32_t c0, c1, c2, c3;
            ldmx4(c0, c1, c2, c3, ka);
#pragma unroll
            for (int nt = 0; nt < 8; nt++) {
                uint32_t x0, x1, x2, x3;
                if (nt < 7) ldmx4(x0, x1, x2, x3, ka + (nt + 1) * 8 * KROW);
                float sv[4] = {0.f, 0.f, 0.f, 0.f};
                mma16816h(sv, qa,     c0, c1);
                mma16816h(sv, qa + 4, c2, c3);
                pf[2 * nt]     = ex2h2(pkh2(sv[0], sv[1]));
                pf[2 * nt + 1] = ex2h2(pkh2(sv[2], sv[3]));
                c0 = x0; c1 = x1; c2 = x2; c3 = x3;
            }
        }
        // ---- row sums ----
        {
            __half2 sa = __hadd2(*(__half2*)&pf[0],  *(__half2*)&pf[2]);
            __half2 sb = __hadd2(*(__half2*)&pf[1],  *(__half2*)&pf[3]);
            sa = __hadd2(sa, __hadd2(*(__half2*)&pf[4],  *(__half2*)&pf[6]));
            sb = __hadd2(sb, __hadd2(*(__half2*)&pf[5],  *(__half2*)&pf[7]));
            sa = __hadd2(sa, __hadd2(*(__half2*)&pf[8],  *(__half2*)&pf[10]));
            sb = __hadd2(sb, __hadd2(*(__half2*)&pf[9],  *(__half2*)&pf[11]));
            sa = __hadd2(sa, __hadd2(*(__half2*)&pf[12], *(__half2*)&pf[14]));
            sb = __hadd2(sb, __hadd2(*(__half2*)&pf[13], *(__half2*)&pf[15]));
            lsum0 += __low2float(sa) + __high2float(sa);
            lsum1 += __low2float(sb) + __high2float(sb);
        }
        // ---- PV phase: V frags double-buffered ----
        {
            const uint32_t va = vb + (lane & 7) * VROW + (lane >> 3) * 16;
            uint32_t r0, r1, r2, r3, r4, r5, r6, r7;
            ldmx4(r0, r1, r2, r3, va);
            ldmx4(r4, r5, r6, r7, va + 64);
#pragma unroll
            for (int ct = 0; ct < 16; ct++) {
                uint32_t y0, y1, y2, y3, y4, y5, y6, y7;
                if (ct < 15) {
                    uint32_t a = va + (ct + 1) * 8 * VROW;
                    ldmx4(y0, y1, y2, y3, a);
                    ldmx4(y4, y5, y6, y7, a + 64);
                }
                float* o = &oacc[ct * 4];
                mma16816h(o, pf + 0,  r0, r1);
                mma16816h(o, pf + 4,  r2, r3);
                mma16816h(o, pf + 8,  r4, r5);
                mma16816h(o, pf + 12, r6, r7);
                r0 = y0; r1 = y1; r2 = y2; r3 = y3;
                r4 = y4; r5 = y5; r6 = y6; r7 = y7;
            }
        }
    }

    lsum0 += __shfl_xor_sync(~0u, lsum0, 1); lsum0 += __shfl_xor_sync(~0u, lsum0, 2);
    lsum1 += __shfl_xor_sync(~0u, lsum1, 1); lsum1 += __shfl_xor_sync(~0u, lsum1, 2);
    __syncthreads();

    float* lbuf = (float*)smem;
    float* obuf = (float*)(smem + SM_K);
    {
        int r0 = w8 * 16 + (lane >> 2);
        if ((lane & 3) == 0) {
            lbuf[r0]     = gamma / lsum0;
            lbuf[r0 + 8] = gamma / lsum1;
        }
    }

    for (int cb = 0; cb < 8; cb++) {
        if ((cb >> 2) == h) {
#pragma unroll
            for (int k = 0; k < 4; k++) {
                int ct = (cb & 3) * 4 + k;
                const float* o = &oacc[ct * 4];
                int chl = k * 8 + 2 * (lane & 3);
                int q0  = w8 * 16 + (lane >> 2);
                obuf[chl * 132 + q0]           = o[0];
                obuf[(chl + 1) * 132 + q0]     = o[1];
                obuf[chl * 132 + q0 + 8]       = o[2];
                obuf[(chl + 1) * 132 + q0 + 8] = o[3];
            }
        }
        __syncthreads();
        {
            int chl = tid >> 4, qq = (tid & 15) * 8;
            int c = cb * 32 + chl;
            const float* xr  = x    + (size_t)c * NN + n0 + qq;
            float*       orw = outp + (size_t)c * NN + n0 + qq;
            const float* ob  = &obuf[chl * 132 + qq];
            const float* lb  = &lbuf[qq];
#pragma unroll
            for (int jj = 0; jj < 2; jj++) {
                float4 xv = *(const float4*)(xr + jj * 4);
                float4 ov;
                ov.x = lb[jj*4+0] * ob[jj*4+0] + xv.x;
                ov.y = lb[jj*4+1] * ob[jj*4+1] + xv.y;
                ov.z = lb[jj*4+2] * ob[jj*4+2] + xv.z;
                ov.w = lb[jj*4+3] * ob[jj*4+3] + xv.w;
                *(float4*)(orw + jj * 4) = ov;
            }
        }
        __syncthreads();
    }
}

// ---------------- launch ----------------
extern "C" void kernel_launch(void* const* d_in, const int* in_sizes, int n_in,
                              void* d_out, int out_size)
{
    const float* x   = (const float*)d_in[0];
    const float* WqA = (const float*)d_in[1];
    const float* bqA = (const float*)d_in[2];
    const float* WkA = (const float*)d_in[3];
    const float* bkA = (const float*)d_in[4];
    const float* WvA = (const float*)d_in[5];
    const float* bvA = (const float*)d_in[6];
    const float* WqB = (const float*)d_in[7];
    const float* bqB = (const float*)d_in[8];
    const float* WkB = (const float*)d_in[9];
    const float* bkB = (const float*)d_in[10];
    const float* WvB = (const float*)d_in[11];
    const float* bvB = (const float*)d_in[12];
    const float* gA  = (const float*)d_in[13];
    const float* gB  = (const float*)d_in[14];
    float* out = (float*)d_out;

    cudaFuncSetAttribute(proj_mma_kernel, cudaFuncAttributeMaxDynamicSharedMemorySize, PROJ_SMEM);
    cudaFuncSetAttribute(attn_mma_kernel, cudaFuncAttributeMaxDynamicSharedMemorySize, SM_TOTAL);

    proj_mma_kernel<<<dim3(64, 5), 256, PROJ_SMEM>>>(x, WqA, bqA, WkA, bkA, WvA, bvA,
                                                     WqB, bqB, WkB, bkB, WvB, bvB);
    attn_mma_kernel<<<dim3(NN / BQ, 2), 512, SM_TOTAL>>>(x, gA, gB, out);
}

// round 17
// speedup vs baseline: 1.0402x; 1.0402x over previous
#include <cuda_runtime.h>
#include <cuda_fp16.h>
#include <cstdint>
#include <math.h>

#define NN    8192
#define CCH   256
#define CD    32
#define BQ    128
#define BK    64
#define NITER 128
#define NSTAGE 4

// attn smem layout (bytes)
#define QROW  80
#define KROW  80
#define VROW  144
#define SM_Q  0
#define KSTG  (BK * KROW)
#define SM_K  10240
#define VSTG  (CCH * VROW)
#define SM_V  (SM_K + NSTAGE * KSTG)
#define SM_TOTAL (SM_V + NSTAGE * VSTG)   // 178176

#define LOG2E 1.4426950408889634f

// proj smem layout
#define PA_STG 6144
#define PB_OFF 12288
#define PSTAGE_OFF 24576
#define PROJ_SMEM (24576 + 34816)   // 59392

// ---------------- scratch (f16 operands) ----------------
__device__ __half g_QA[NN * CD];
__device__ __half g_KA[NN * CD];
__device__ __half g_QB[NN * CD];
__device__ __half g_KB[NN * CD];
__device__ __half g_VAb[CCH * NN];
__device__ __half g_VBb[CCH * NN];

// ---------------- PTX helpers ----------------
__device__ __forceinline__ uint32_t smem_u32(const void* p) {
    uint32_t a;
    asm("{ .reg .u64 t; cvta.to.shared.u64 t, %1; cvt.u32.u64 %0, t; }" : "=r"(a) : "l"(p));
    return a;
}
__device__ __forceinline__ void cp16(uint32_t dst, const void* src) {
    asm volatile("cp.async.cg.shared.global [%0], [%1], 16;" :: "r"(dst), "l"(src));
}
__device__ __forceinline__ void cp_commit() { asm volatile("cp.async.commit_group;" ::: "memory"); }
__device__ __forceinline__ void cp_wait2()  { asm volatile("cp.async.wait_group 2;"  ::: "memory"); }

__device__ __forceinline__ void ldmx4(uint32_t& r0, uint32_t& r1, uint32_t& r2, uint32_t& r3,
                                      uint32_t a) {
    asm volatile("ldmatrix.sync.aligned.m8n8.x4.shared.b16 {%0,%1,%2,%3}, [%4];"
        : "=r"(r0), "=r"(r1), "=r"(r2), "=r"(r3) : "r"(a));
}
__device__ __forceinline__ void mma16816h(float* c, const uint32_t* a, uint32_t b0, uint32_t b1) {
    asm volatile("mma.sync.aligned.m16n8k16.row.col.f32.f16.f16.f32 "
        "{%0,%1,%2,%3}, {%4,%5,%6,%7}, {%8,%9}, {%0,%1,%2,%3};"
        : "+f"(c[0]), "+f"(c[1]), "+f"(c[2]), "+f"(c[3])
        : "r"(a[0]), "r"(a[1]), "r"(a[2]), "r"(a[3]), "r"(b0), "r"(b1));
}
__device__ __forceinline__ uint32_t pkh2(float lo, float hi) {
    uint32_t d;
    asm("cvt.rn.f16x2.f32 %0, %1, %2;" : "=r"(d) : "f"(hi), "f"(lo));
    return d;
}
__device__ __forceinline__ uint32_t ex2h2(uint32_t a) {
    uint32_t d;
    asm("ex2.approx.f16x2 %0, %1;" : "=r"(d) : "r"(a));
    return d;
}
__device__ __forceinline__ void sts32(uint32_t a, uint32_t v) {
    asm volatile("st.shared.b32 [%0], %1;" :: "r"(a), "r"(v) : "memory");
}
__device__ __forceinline__ void sts16(uint32_t a, unsigned short v) {
    asm volatile("st.shared.b16 [%0], %1;" :: "r"(a), "h"(v) : "memory");
}
__device__ __forceinline__ uint4 lds128(uint32_t a) {
    uint4 v;
    asm volatile("ld.shared.v4.u32 {%0,%1,%2,%3}, [%4];"
        : "=r"(v.x), "=r"(v.y), "=r"(v.z), "=r"(v.w) : "r"(a));
    return v;
}

// ---------------- tensor-core projections ----------------
__global__ void __launch_bounds__(256, 2)
proj_mma_kernel(const float* __restrict__ x,
                const float* __restrict__ WqA, const float* __restrict__ bqA,
                const float* __restrict__ WkA, const float* __restrict__ bkA,
                const float* __restrict__ WvA, const float* __restrict__ bvA,
                const float* __restrict__ WqB, const float* __restrict__ bqB,
                const float* __restrict__ WkB, const float* __restrict__ bkB,
                const float* __restrict__ WvB, const float* __restrict__ bvB)
{
    extern __shared__ __align__(128) char psm[];
    const uint32_t smb = smem_u32(psm);
    const int tid  = threadIdx.x;
    const int lane = tid & 31;
    const int wid  = tid >> 5;
    const int mg   = wid & 3;
    const int nh   = wid >> 2;
    const int by   = blockIdx.y;
    const int n0   = blockIdx.x * 128;

    const int rA  = tid >> 3;
    const int j2  = tid & 7;
    const int ct2 = tid >> 7;
    const int xn  = n0 + (tid & 127);
    const float* aptr[4];
    int rowbase = 0;
    const float* bv = 0;
    if (by == 0) {
        aptr[0] = WqA + rA * CCH; aptr[1] = WkA + rA * CCH;
        aptr[2] = WqB + rA * CCH; aptr[3] = WkB + rA * CCH;
    } else {
        const float* Wv = (by <= 2) ? WvA : WvB;
        bv = (by <= 2) ? bvA : bvB;
        rowbase = ((by - 1) & 1) * 128;
#pragma unroll
        for (int i = 0; i < 4; i++) aptr[i] = Wv + (rowbase + rA + i * 32) * CCH;
    }

    float oacc[64];
#pragma unroll
    for (int i = 0; i < 64; i++) oacc[i] = 0.f;

    {
#pragma unroll
        for (int i = 0; i < 4; i++) {
            float2 w2 = *(const float2*)(aptr[i] + 2 * j2);
            sts32(smb + (rA + i * 32) * 48 + j2 * 4, pkh2(w2.x, w2.y));
        }
#pragma unroll
        for (int i = 0; i < 4; i++) {
            int cp = i * 4 + ct2 * 2;
            float v0 = x[(size_t)cp * NN + xn];
            float v1 = x[(size_t)(cp + 1) * NN + xn];
            sts32(smb + PB_OFF + (tid & 127) * 48 + cp * 2, pkh2(v0, v1));
        }
    }
    __syncthreads();

#pragma unroll 1
    for (int kc = 0; kc < 16; kc++) {
        float2 wA[4]; float xb0[4], xb1[4];
        if (kc < 15) {
            int k1 = (kc + 1) * 16;
#pragma unroll
            for (int i = 0; i < 4; i++) wA[i] = *(const float2*)(aptr[i] + k1 + 2 * j2);
#pragma unroll
            for (int i = 0; i < 4; i++) {
                int cp = i * 4 + ct2 * 2;
                xb0[i] = x[(size_t)(k1 + cp) * NN + xn];
                xb1[i] = x[(size_t)(k1 + cp + 1) * NN + xn];
            }
        }
        const uint32_t Ab = smb + (kc & 1) * PA_STG;
        const uint32_t Bb = smb + PB_OFF + (kc & 1) * PA_STG;

        uint32_t a0[4], a1[4];
        uint32_t aa = Ab + (mg * 32 + (lane & 15)) * 48 + (lane >> 4) * 16;
        ldmx4(a0[0], a0[1], a0[2], a0[3], aa);
        ldmx4(a1[0], a1[1], a1[2], a1[3], aa + 16 * 48);
#pragma unroll
        for (int ng = 0; ng < 4; ng++) {
            uint32_t b0, b1, b2, b3;
            uint32_t ba = Bb + (nh * 64 + ng * 16 + (lane & 7) + ((lane >> 4) & 1) * 8) * 48
                        + ((lane >> 3) & 1) * 16;
            ldmx4(b0, b1, b2, b3, ba);
            mma16816h(&oacc[(ng * 2 + 0) * 4],      a0, b0, b1);
            mma16816h(&oacc[(ng * 2 + 1) * 4],      a0, b2, b3);
            mma16816h(&oacc[(8 + ng * 2 + 0) * 4],  a1, b0, b1);
            mma16816h(&oacc[(8 + ng * 2 + 1) * 4],  a1, b2, b3);
        }

        if (kc < 15) {
            const uint32_t Aw = smb + ((kc + 1) & 1) * PA_STG;
            const uint32_t Bw = smb + PB_OFF + ((kc + 1) & 1) * PA_STG;
#pragma unroll
            for (int i = 0; i < 4; i++)
                sts32(Aw + (rA + i * 32) * 48 + j2 * 4, pkh2(wA[i].x, wA[i].y));
#pragma unroll
            for (int i = 0; i < 4; i++) {
                int cp = i * 4 + ct2 * 2;
                sts32(Bw + (tid & 127) * 48 + cp * 2, pkh2(xb0[i], xb1[i]));
            }
        }
        __syncthreads();
    }

    if (by == 0) {
        const float* bArr[4] = {bqA, bkA, bqB, bkB};
        const float sc = (mg == 0 || mg == 2) ? LOG2E : 1.f;
        const uint32_t stg = smb + PSTAGE_OFF;
#pragma unroll
        for (int m2 = 0; m2 < 2; m2++) {
#pragma unroll
            for (int s8 = 0; s8 < 2; s8++) {
                int cl = m2 * 16 + (lane >> 2) + s8 * 8;
                int c  = mg * 32 + cl;
                float bb = bArr[mg][cl];
#pragma unroll
                for (int nt = 0; nt < 8; nt++) {
                    const float* o = &oacc[(m2 * 8 + nt) * 4];
                    int n = nh * 64 + nt * 8 + 2 * (lane & 3);
                    float v0 = (o[s8 * 2]     + bb) * sc;
                    float v1 = (o[s8 * 2 + 1] + bb) * sc;
                    sts16(stg + n * 272 + c * 2,       __half_as_ushort(__float2half_rn(v0)));
                    sts16(stg + (n + 1) * 272 + c * 2, __half_as_ushort(__float2half_rn(v1)));
                }
            }
        }
        __syncthreads();
        __half* gq[4] = {g_QA, g_KA, g_QB, g_KB};
#pragma unroll
        for (int i = 0; i < 8; i++) {
            int id = i * 256 + tid;
            int n = id >> 4, c16 = id & 15;
            uint4 v = lds128(stg + n * 272 + c16 * 16);
            int c = c16 * 8;
            __half* gp = gq[c >> 5] + (size_t)(n0 + n) * CD + (c & 31);
            *(uint4*)gp = v;
        }
    } else {
        __half* gV = (by <= 2) ? g_VAb : g_VBb;
#pragma unroll
        for (int m2 = 0; m2 < 2; m2++) {
#pragma unroll
            for (int s8 = 0; s8 < 2; s8++) {
                int c = mg * 32 + m2 * 16 + (lane >> 2) + s8 * 8;
                float bb = bv[rowbase + c];
#pragma unroll
                for (int nt = 0; nt < 8; nt++) {
                    const float* o = &oacc[(m2 * 8 + nt) * 4];
                    int n = nh * 64 + nt * 8 + 2 * (lane & 3);
                    __half2 hv = __floats2half2_rn(o[s8 * 2] + bb, o[s8 * 2 + 1] + bb);
                    *(__half2*)(gV + (size_t)(rowbase + c) * NN + n0 + n) = hv;
                }
            }
        }
    }
}

// ---------------- K/V tile loader (512 threads) ----------------
__device__ __forceinline__ void load_kv(uint32_t smb, int st, int t,
                                        const __half* __restrict__ Kg,
                                        const __half* __restrict__ Vg,
                                        int tid)
{
    const int m0 = t * BK;
    if (tid < 256) {
        int r = tid >> 2, j = tid & 3;
        cp16(smb + SM_K + st * KSTG + r * KROW + j * 16,
             Kg + (size_t)(m0 + r) * CD + j * 8);
    }
#pragma unroll
    for (int i = 0; i < 4; i++) {
        int idx = tid + i * 512;
        int r = idx >> 3, j = idx & 7;
        cp16(smb + SM_V + st * VSTG + r * VROW + j * 16,
             Vg + (size_t)r * NN + m0 + j * 8);
    }
}

// ---------------- fused mma.sync flash attention (R8 champion) ----------------
extern "C" __global__ void __launch_bounds__(512, 1)
attn_mma_kernel(const float* __restrict__ x,
                const float* __restrict__ gA, const float* __restrict__ gB,
                float* __restrict__ out)
{
    extern __shared__ __align__(128) char smem[];
    const uint32_t smb = smem_u32(smem);
    const int tid  = threadIdx.x;
    const int wid  = tid >> 5;
    const int lane = tid & 31;
    const int h    = wid >> 3;
    const int w8   = wid & 7;
    const int n0   = blockIdx.x * BQ;

    const __half *Qg, *Kg, *Vg; float gamma; float* outp;
    if (blockIdx.y == 0) { Qg = g_QA; Kg = g_KB; Vg = g_VBb; gamma = gA[0]; outp = out; }
    else                 { Qg = g_QB; Kg = g_KA; Vg = g_VAb; gamma = gB[0]; outp = out + (size_t)CCH * NN; }

    {
        int r = tid >> 2, j = tid & 3;
        cp16(smb + SM_Q + r * QROW + j * 16, Qg + (size_t)(n0 + r) * CD + j * 8);
    }
    load_kv(smb, 0, 0, Kg, Vg, tid); cp_commit();
    load_kv(smb, 1, 1, Kg, Vg, tid); cp_commit();
    load_kv(smb, 2, 2, Kg, Vg, tid); cp_commit();

    uint32_t qa[8];
    float oacc[64];
#pragma unroll
    for (int i = 0; i < 64; i++) oacc[i] = 0.f;
    float lsum0 = 0.f, lsum1 = 0.f;

#pragma unroll 1
    for (int t = 0; t < NITER; t++) {
        cp_wait2();
        __syncthreads();

        if (t == 0) {
            uint32_t a0 = smb + SM_Q + (w8 * 16 + (lane & 15)) * QROW + (lane >> 4) * 16;
            ldmx4(qa[0], qa[1], qa[2], qa[3], a0);
            ldmx4(qa[4], qa[5], qa[6], qa[7], a0 + 32);
        }
        if (t + 3 < NITER) load_kv(smb, (t + 3) & 3, t + 3, Kg, Vg, tid);
        cp_commit();

        const uint32_t kb = smb + SM_K + (t & 3) * KSTG;
        const uint32_t vb = smb + SM_V + (t & 3) * VSTG + h * 128 * VROW;

        // ---- S phase: K frags double-buffered, converted to pf per-nt ----
        uint32_t pf[16];
        {
            const uint32_t ka = kb + (lane & 7) * KROW + (lane >> 3) * 16;
            uint32_t c0, c1, c2, c3;
            ldmx4(c0, c1, c2, c3, ka);
#pragma unroll
            for (int nt = 0; nt < 8; nt++) {
                uint32_t x0, x1, x2, x3;
                if (nt < 7) ldmx4(x0, x1, x2, x3, ka + (nt + 1) * 8 * KROW);
                float sv[4] = {0.f, 0.f, 0.f, 0.f};
                mma16816h(sv, qa,     c0, c1);
                mma16816h(sv, qa + 4, c2, c3);
                pf[2 * nt]     = ex2h2(pkh2(sv[0], sv[1]));
                pf[2 * nt + 1] = ex2h2(pkh2(sv[2], sv[3]));
                c0 = x0; c1 = x1; c2 = x2; c3 = x3;
            }
        }
        // ---- row sums ----
        {
            __half2 sa = __hadd2(*(__half2*)&pf[0],  *(__half2*)&pf[2]);
            __half2 sb = __hadd2(*(__half2*)&pf[1],  *(__half2*)&pf[3]);
            sa = __hadd2(sa, __hadd2(*(__half2*)&pf[4],  *(__half2*)&pf[6]));
            sb = __hadd2(sb, __hadd2(*(__half2*)&pf[5],  *(__half2*)&pf[7]));
            sa = __hadd2(sa, __hadd2(*(__half2*)&pf[8],  *(__half2*)&pf[10]));
            sb = __hadd2(sb, __hadd2(*(__half2*)&pf[9],  *(__half2*)&pf[11]));
            sa = __hadd2(sa, __hadd2(*(__half2*)&pf[12], *(__half2*)&pf[14]));
            sb = __hadd2(sb, __hadd2(*(__half2*)&pf[13], *(__half2*)&pf[15]));
            lsum0 += __low2float(sa) + __high2float(sa);
            lsum1 += __low2float(sb) + __high2float(sb);
        }
        // ---- PV phase: V frags double-buffered ----
        {
            const uint32_t va = vb + (lane & 7) * VROW + (lane >> 3) * 16;
            uint32_t r0, r1, r2, r3, r4, r5, r6, r7;
            ldmx4(r0, r1, r2, r3, va);
            ldmx4(r4, r5, r6, r7, va + 64);
#pragma unroll
            for (int ct = 0; ct < 16; ct++) {
                uint32_t y0, y1, y2, y3, y4, y5, y6, y7;
                if (ct < 15) {
                    uint32_t a = va + (ct + 1) * 8 * VROW;
                    ldmx4(y0, y1, y2, y3, a);
                    ldmx4(y4, y5, y6, y7, a + 64);
                }
                float* o = &oacc[ct * 4];
                mma16816h(o, pf + 0,  r0, r1);
                mma16816h(o, pf + 4,  r2, r3);
                mma16816h(o, pf + 8,  r4, r5);
                mma16816h(o, pf + 12, r6, r7);
                r0 = y0; r1 = y1; r2 = y2; r3 = y3;
                r4 = y4; r5 = y5; r6 = y6; r7 = y7;
            }
        }
    }

    lsum0 += __shfl_xor_sync(~0u, lsum0, 1); lsum0 += __shfl_xor_sync(~0u, lsum0, 2);
    lsum1 += __shfl_xor_sync(~0u, lsum1, 1); lsum1 += __shfl_xor_sync(~0u, lsum1, 2);
    __syncthreads();

    float* lbuf = (float*)smem;
    float* obuf = (float*)(smem + SM_K);
    {
        int r0 = w8 * 16 + (lane >> 2);
        if ((lane & 3) == 0) {
            lbuf[r0]     = gamma / lsum0;
            lbuf[r0 + 8] = gamma / lsum1;
        }
    }

    for (int cb = 0; cb < 8; cb++) {
        if ((cb >> 2) == h) {
#pragma unroll
            for (int k = 0; k < 4; k++) {
                int ct = (cb & 3) * 4 + k;
                const float* o = &oacc[ct * 4];
                int chl = k * 8 + 2 * (lane & 3);
                int q0  = w8 * 16 + (lane >> 2);
                obuf[chl * 132 + q0]           = o[0];
                obuf[(chl + 1) * 132 + q0]     = o[1];
                obuf[chl * 132 + q0 + 8]       = o[2];
                obuf[(chl + 1) * 132 + q0 + 8] = o[3];
            }
        }
        __syncthreads();
        {
            int chl = tid >> 4, qq = (tid & 15) * 8;
            int c = cb * 32 + chl;
            const float* xr  = x    + (size_t)c * NN + n0 + qq;
            float*       orw = outp + (size_t)c * NN + n0 + qq;
            const float* ob  = &obuf[chl * 132 + qq];
            const float* lb  = &lbuf[qq];
#pragma unroll
            for (int jj = 0; jj < 2; jj++) {
                float4 xv = *(const float4*)(xr + jj * 4);
                float4 ov;
                ov.x = lb[jj*4+0] * ob[jj*4+0] + xv.x;
                ov.y = lb[jj*4+1] * ob[jj*4+1] + xv.y;
                ov.z = lb[jj*4+2] * ob[jj*4+2] + xv.z;
                ov.w = lb[jj*4+3] * ob[jj*4+3] + xv.w;
                *(float4*)(orw + jj * 4) = ov;
            }
        }
        __syncthreads();
    }
}

// ---------------- launch ----------------
extern "C" void kernel_launch(void* const* d_in, const int* in_sizes, int n_in,
                              void* d_out, int out_size)
{
    const float* x   = (const float*)d_in[0];
    const float* WqA = (const float*)d_in[1];
    const float* bqA = (const float*)d_in[2];
    const float* WkA = (const float*)d_in[3];
    const float* bkA = (const float*)d_in[4];
    const float* WvA = (const float*)d_in[5];
    const float* bvA = (const float*)d_in[6];
    const float* WqB = (const float*)d_in[7];
    const float* bqB = (const float*)d_in[8];
    const float* WkB = (const float*)d_in[9];
    const float* bkB = (const float*)d_in[10];
    const float* WvB = (const float*)d_in[11];
    const float* bvB = (const float*)d_in[12];
    const float* gA  = (const float*)d_in[13];
    const float* gB  = (const float*)d_in[14];
    float* out = (float*)d_out;

    cudaFuncSetAttribute(proj_mma_kernel, cudaFuncAttributeMaxDynamicSharedMemorySize, PROJ_SMEM);
    cudaFuncSetAttribute(attn_mma_kernel, cudaFuncAttributeMaxDynamicSharedMemorySize, SM_TOTAL);

    proj_mma_kernel<<<dim3(64, 5), 256, PROJ_SMEM>>>(x, WqA, bqA, WkA, bkA, WvA, bvA,
                                                     WqB, bqB, WkB, bkB, WvB, bvB);
    attn_mma_kernel<<<dim3(NN / BQ, 2), 512, SM_TOTAL>>>(x, gA, gB, out);
}